// round 13
// baseline (speedup 1.0000x reference)
#include <cuda_runtime.h>
#include <math.h>

#define NPIX 3136
#define HH 56
#define WW 56
#define BB 4
#define CC 256
#define ICH 128
#define GG 4
#define DD 32
#define C4 64
#define EPSB 1e-5f
#define SHIFT 10.0f
#define GS 72  // shared input tile stride (conflict-free for mma B-frag gather)

// ---------------- scratch ----------------
__device__ float d_gbuf[BB * ICH * NPIX];
__device__ float d_tbuf[BB * ICH * NPIX];
__device__ float d_pbuf[BB * ICH * NPIX];
__device__ float d_ybuf[BB * ICH * NPIX];
__device__ float d_zbuf[BB * CC * NPIX];
__device__ float d_o1buf[BB * C4 * NPIX];
__device__ float d_o2buf[BB * C4 * NPIX];

__device__ __forceinline__ float tf32_round(float v) {
  unsigned u;
  asm("cvt.rna.tf32.f32 %0, %1;" : "=r"(u) : "f"(v));
  return __uint_as_float(u);
}
__device__ __forceinline__ unsigned tf32_bits(float v) {
  unsigned u;
  asm("cvt.rna.tf32.f32 %0, %1;" : "=r"(u) : "f"(v));
  return u;
}
__device__ __forceinline__ void mma_tf32(float c[4], const unsigned a[4],
                                         unsigned b0, unsigned b1) {
  asm volatile(
      "mma.sync.aligned.m16n8k8.row.col.f32.tf32.tf32.f32 "
      "{%0,%1,%2,%3}, {%4,%5,%6,%7}, {%8,%9}, {%0,%1,%2,%3};"
      : "+f"(c[0]), "+f"(c[1]), "+f"(c[2]), "+f"(c[3])
      : "r"(a[0]), "r"(a[1]), "r"(a[2]), "r"(a[3]), "r"(b0), "r"(b1));
}
__device__ __forceinline__ void cp16(unsigned saddr, const void* gaddr) {
  asm volatile("cp.async.ca.shared.global [%0], [%1], 16;\n" ::"r"(saddr),
               "l"(gaddr));
}
#define CP_COMMIT asm volatile("cp.async.commit_group;\n" ::: "memory")
#define CP_WAIT0 asm volatile("cp.async.wait_group 0;\n" ::: "memory")
#define CP_WAIT1 asm volatile("cp.async.wait_group 1;\n" ::: "memory")

// ---------------- GEMM core: 64 Cout rows x 64 px cols per block (R4) --------
__device__ __forceinline__ void gemm_core(const float* __restrict__ inb,
                                          const float* __restrict__ w, int Cin,
                                          int o0, int tid, float* s_in,
                                          float (&c)[8][4]) {
  const int lane = tid & 31;
  const int lg = lane >> 2, lt = lane & 3;
  const int lr = tid >> 4;         // 0..7
  const int lc = (tid & 15) * 4;   // 0..60

  for (int k0 = 0; k0 < Cin; k0 += 32) {
    __syncthreads();
#pragma unroll
    for (int i = 0; i < 4; i++) {
      int r = i * 8 + lr;
      float4 v = *(const float4*)(inb + (size_t)(k0 + r) * NPIX + lc);
      v.x = tf32_round(v.x);
      v.y = tf32_round(v.y);
      v.z = tf32_round(v.z);
      v.w = tf32_round(v.w);
      *(float4*)&s_in[r * GS + lc] = v;
    }
    __syncthreads();
#pragma unroll
    for (int ks = 0; ks < 4; ks++) {
      int kk = k0 + ks * 8;
      unsigned a[4];
      a[0] = tf32_bits(w[(size_t)(o0 + lg) * Cin + kk + lt]);
      a[1] = tf32_bits(w[(size_t)(o0 + lg + 8) * Cin + kk + lt]);
      a[2] = tf32_bits(w[(size_t)(o0 + lg) * Cin + kk + lt + 4]);
      a[3] = tf32_bits(w[(size_t)(o0 + lg + 8) * Cin + kk + lt + 4]);
#pragma unroll
      for (int nt = 0; nt < 8; nt++) {
        unsigned b0 = __float_as_uint(s_in[(ks * 8 + lt) * GS + nt * 8 + lg]);
        unsigned b1 =
            __float_as_uint(s_in[(ks * 8 + lt + 4) * GS + nt * 8 + lg]);
        mma_tf32(c[nt], a, b0, b1);
      }
    }
  }
}

// ---------------- fused g/theta/phi GEMM (MODE 0: +bias, tf32 round) ---------
__global__ __launch_bounds__(128) void gtp_k(
    const float* __restrict__ x, const float* __restrict__ w0,
    const float* __restrict__ bi0, const float* __restrict__ w1,
    const float* __restrict__ bi1, const float* __restrict__ w2,
    const float* __restrict__ bi2, float* __restrict__ out0,
    float* __restrict__ out1, float* __restrict__ out2) {
  __shared__ float s_in[32 * GS];
  const int tid = threadIdx.x;
  const int lane = tid & 31, wp = tid >> 5;
  const int lg = lane >> 2, lt = lane & 3;
  const int b = blockIdx.x / 49;
  const int px0 = (blockIdx.x % 49) * 64;
  const int sel = blockIdx.y >> 1;
  const int o0 = (blockIdx.y & 1) * 64 + wp * 16;

  const float* w = sel == 0 ? w0 : (sel == 1 ? w1 : w2);
  const float* bi = sel == 0 ? bi0 : (sel == 1 ? bi1 : bi2);
  float* out = sel == 0 ? out0 : (sel == 1 ? out1 : out2);

  float c[8][4] = {};
  gemm_core(x + (size_t)b * CC * NPIX + px0, w, CC, o0, tid, s_in, c);

  int r0 = o0 + lg, r1 = r0 + 8;
  float bb0 = bi[r0], bb1 = bi[r1];
  float* ob0 = out + ((size_t)b * ICH + r0) * NPIX + px0;
  float* ob1 = out + ((size_t)b * ICH + r1) * NPIX + px0;
#pragma unroll
  for (int nt = 0; nt < 8; nt++) {
    int n = nt * 8 + 2 * lt;
    float2 v0 =
        make_float2(tf32_round(c[nt][0] + bb0), tf32_round(c[nt][1] + bb0));
    float2 v1 =
        make_float2(tf32_round(c[nt][2] + bb1), tf32_round(c[nt][3] + bb1));
    *(float2*)(ob0 + n) = v0;
    *(float2*)(ob1 + n) = v1;
  }
}

// ---------------- generic 1x1 GEMM with epilogues (R4) ----------------
// MODE 1: +bias, BN, +res, ReLU   MODE 2: BN, ReLU   MODE 3: BN, +res, ReLU
template <int MODE>
__global__ __launch_bounds__(128) void gemm1x1_k(
    const float* __restrict__ in, const float* __restrict__ w,
    const float* __restrict__ bias, const float* __restrict__ bns,
    const float* __restrict__ bnb, const float* __restrict__ bnm,
    const float* __restrict__ bnv, const float* __restrict__ res,
    float* __restrict__ out, int Cin, int Cout) {
  __shared__ float s_in[32 * GS];
  const int tid = threadIdx.x;
  const int lane = tid & 31, wp = tid >> 5;
  const int lg = lane >> 2, lt = lane & 3;
  const int b = blockIdx.x / 49;
  const int px0 = (blockIdx.x % 49) * 64;
  const int o0 = blockIdx.y * 64 + wp * 16;

  float c[8][4] = {};
  gemm_core(in + (size_t)b * Cin * NPIX + px0, w, Cin, o0, tid, s_in, c);

  int r0 = o0 + lg, r1 = r0 + 8;
  float bi0 = (MODE == 1) ? bias[r0] : 0.f;
  float bi1 = (MODE == 1) ? bias[r1] : 0.f;
  float i0 = bns[r0] * rsqrtf(bnv[r0] + EPSB);
  float a0 = bnb[r0] - bnm[r0] * i0 + bi0 * i0;
  float i1 = bns[r1] * rsqrtf(bnv[r1] + EPSB);
  float a1 = bnb[r1] - bnm[r1] * i1 + bi1 * i1;

  float* ob0 = out + ((size_t)b * Cout + r0) * NPIX + px0;
  float* ob1 = out + ((size_t)b * Cout + r1) * NPIX + px0;
  const float* rb0 = res ? res + ((size_t)b * Cout + r0) * NPIX + px0 : nullptr;
  const float* rb1 = res ? res + ((size_t)b * Cout + r1) * NPIX + px0 : nullptr;
#pragma unroll
  for (int nt = 0; nt < 8; nt++) {
    int n = nt * 8 + 2 * lt;
    float v00 = c[nt][0] * i0 + a0;
    float v01 = c[nt][1] * i0 + a0;
    float v10 = c[nt][2] * i1 + a1;
    float v11 = c[nt][3] * i1 + a1;
    if (MODE == 1 || MODE == 3) {
      float2 q0 = *(const float2*)(rb0 + n);
      float2 q1 = *(const float2*)(rb1 + n);
      v00 += q0.x;
      v01 += q0.y;
      v10 += q1.x;
      v11 += q1.y;
    }
    *(float2*)(ob0 + n) = make_float2(fmaxf(v00, 0.f), fmaxf(v01, 0.f));
    *(float2*)(ob1 + n) = make_float2(fmaxf(v10, 0.f), fmaxf(v11, 0.f));
  }
}

// ---------------- 3x3 conv as implicit GEMM (R4) ----------------
__global__ __launch_bounds__(128) void conv3x3_k(
    const float* __restrict__ in, const float* __restrict__ w,
    const float* __restrict__ bns, const float* __restrict__ bnb,
    const float* __restrict__ bnm, const float* __restrict__ bnv,
    float* __restrict__ out) {
  __shared__ float s_in[32 * GS];
  const int tid = threadIdx.x;
  const int lane = tid & 31, wp = tid >> 5;
  const int lg = lane >> 2, lt = lane & 3;
  const int b = blockIdx.x / 49;
  const int px0 = (blockIdx.x % 49) * 64;
  const int o0 = wp * 16;
  const float* inb = in + (size_t)b * C4 * NPIX;

  const int j = tid & 63;
  const int crow = tid >> 6;
  const int pix = px0 + j;
  const int ph = pix / WW, pw = pix % WW;

  float c[8][4] = {};

#pragma unroll
  for (int kk = 0; kk < 9; kk++) {
    const int dy = kk / 3 - 1, dx = kk % 3 - 1;
    const int hs = ph + dy, ws = pw + dx;
    const bool valid = ((unsigned)hs < HH) && ((unsigned)ws < WW);
    const int src = hs * WW + ws;
#pragma unroll
    for (int k0 = 0; k0 < C4; k0 += 32) {
      __syncthreads();
#pragma unroll
      for (int i = 0; i < 16; i++) {
        int cl = crow + 2 * i;
        float v = valid ? inb[(size_t)(k0 + cl) * NPIX + src] : 0.f;
        s_in[cl * GS + j] = tf32_round(v);
      }
      __syncthreads();
#pragma unroll
      for (int ks = 0; ks < 4; ks++) {
        int ic = k0 + ks * 8;
        unsigned a[4];
        a[0] = tf32_bits(w[(size_t)(o0 + lg) * (C4 * 9) + (ic + lt) * 9 + kk]);
        a[1] =
            tf32_bits(w[(size_t)(o0 + lg + 8) * (C4 * 9) + (ic + lt) * 9 + kk]);
        a[2] =
            tf32_bits(w[(size_t)(o0 + lg) * (C4 * 9) + (ic + lt + 4) * 9 + kk]);
        a[3] = tf32_bits(
            w[(size_t)(o0 + lg + 8) * (C4 * 9) + (ic + lt + 4) * 9 + kk]);
#pragma unroll
        for (int nt = 0; nt < 8; nt++) {
          unsigned b0 = __float_as_uint(s_in[(ks * 8 + lt) * GS + nt * 8 + lg]);
          unsigned b1 =
              __float_as_uint(s_in[(ks * 8 + lt + 4) * GS + nt * 8 + lg]);
          mma_tf32(c[nt], a, b0, b1);
        }
      }
    }
  }

  int r0 = o0 + lg, r1 = r0 + 8;
  float i0 = bns[r0] * rsqrtf(bnv[r0] + EPSB);
  float a0 = bnb[r0] - bnm[r0] * i0;
  float i1 = bns[r1] * rsqrtf(bnv[r1] + EPSB);
  float a1 = bnb[r1] - bnm[r1] * i1;
  float* ob0 = out + ((size_t)b * C4 + r0) * NPIX + px0;
  float* ob1 = out + ((size_t)b * C4 + r1) * NPIX + px0;
#pragma unroll
  for (int nt = 0; nt < 8; nt++) {
    int n = nt * 8 + 2 * lt;
    *(float2*)(ob0 + n) = make_float2(fmaxf(c[nt][0] * i0 + a0, 0.f),
                                      fmaxf(c[nt][1] * i0 + a0, 0.f));
    *(float2*)(ob1 + n) = make_float2(fmaxf(c[nt][2] * i1 + a1, 0.f),
                                      fmaxf(c[nt][3] * i1 + a1, 0.f));
  }
}

// ---- tf32 mma flash attention: R4 body + FULL cp.async double buffering ----
// p and g both double-buffered; {p,g}(kt+1) issued as one group at tile kt,
// hidden behind a full tile of compute. Dynamic smem 55.3 KB -> 4 blocks/SM.
#define SP_STRIDE 72
#define SG_STRIDE 68
#define PR_STRIDE 76
#define APa 0
#define APb (32 * SP_STRIDE)                 // 2304
#define AGa (2 * 32 * SP_STRIDE)             // 4608
#define AGb (AGa + 32 * SG_STRIDE)           // 6784
#define APR (AGb + 32 * SG_STRIDE)           // 8960
#define SMEM_ATT (APR + 64 * PR_STRIDE)      // 13824 floats = 55296 B

__global__ __launch_bounds__(64) void attn_k(const float* __restrict__ t,
                                             const float* __restrict__ p,
                                             const float* __restrict__ g,
                                             float* __restrict__ y) {
  extern __shared__ float sm[];
  const unsigned sb = (unsigned)__cvta_generic_to_shared(sm);

  const int tid = threadIdx.x;
  const int lane = tid & 31;
  const int wp = tid >> 5;
  const int lg = lane >> 2;
  const int lt = lane & 3;
  const int q0w = wp * 32;
  const int n0 = blockIdx.x * 64;
  const int gi = blockIdx.y;
  const int b = blockIdx.z;
  const size_t ro = ((size_t)b * ICH + gi * DD) * NPIX;

  const int lrow4 = tid >> 4;       // 0..3
  const int lcol = (tid & 15) * 4;  // 0..60

  // prologue: issue {p,g}(0) into buffers A
  {
#pragma unroll
    for (int i = 0; i < 8; i++) {
      int r = i * 4 + lrow4;
      cp16(sb + (APa + r * SP_STRIDE + lcol) * 4,
           p + ro + (size_t)r * NPIX + lcol);
      cp16(sb + (AGa + r * SG_STRIDE + lcol) * 4,
           g + ro + (size_t)r * NPIX + lcol);
    }
    CP_COMMIT;
  }

  // Q fragments straight from gmem (overlaps prologue loads)
  unsigned qa[2][4][4];
#pragma unroll
  for (int r = 0; r < 2; r++) {
    int qb = n0 + q0w + r * 16;
#pragma unroll
    for (int ks = 0; ks < 4; ks++) {
      int d0 = ks * 8 + lt;
      qa[r][ks][0] = __float_as_uint(t[ro + (size_t)d0 * NPIX + qb + lg]);
      qa[r][ks][1] = __float_as_uint(t[ro + (size_t)d0 * NPIX + qb + lg + 8]);
      qa[r][ks][2] = __float_as_uint(t[ro + (size_t)(d0 + 4) * NPIX + qb + lg]);
      qa[r][ks][3] =
          __float_as_uint(t[ro + (size_t)(d0 + 4) * NPIX + qb + lg + 8]);
    }
  }

  float c[2][4][4];
#pragma unroll
  for (int r = 0; r < 2; r++)
#pragma unroll
    for (int dt = 0; dt < 4; dt++)
#pragma unroll
      for (int i = 0; i < 4; i++) c[r][dt][i] = 0.f;
  float Ls[2][2] = {{0.f, 0.f}, {0.f, 0.f}};

  const int NT = NPIX / 64;  // 49
  for (int kt = 0; kt < NT; kt++) {
    const int pb = (kt & 1) ? APb : APa;
    const int gb = (kt & 1) ? AGb : AGa;
    // retire all reads of the alternate buffers (used at kt-1) before refill
    __syncthreads();
    if (kt + 1 < NT) {
      const int pn = (kt & 1) ? APa : APb;
      const int gn = (kt & 1) ? AGa : AGb;
      const int k1 = (kt + 1) * 64;
#pragma unroll
      for (int i = 0; i < 8; i++) {
        int r = i * 4 + lrow4;
        cp16(sb + (pn + r * SP_STRIDE + lcol) * 4,
             p + ro + (size_t)r * NPIX + k1 + lcol);
        cp16(sb + (gn + r * SG_STRIDE + lcol) * 4,
             g + ro + (size_t)r * NPIX + k1 + lcol);
      }
      CP_COMMIT;
      CP_WAIT1;  // group kt complete; group kt+1 in flight
    } else {
      CP_WAIT0;
    }
    __syncthreads();  // cross-thread visibility of async arrivals

    // ---- QK + exp + stage probs (R4 body, buffer pb) ----
#pragma unroll
    for (int nt = 0; nt < 8; nt++) {
      float s0[4] = {0.f, 0.f, 0.f, 0.f};
      float s1[4] = {0.f, 0.f, 0.f, 0.f};
#pragma unroll
      for (int ks = 0; ks < 4; ks++) {
        unsigned b0 = __float_as_uint(
            sm[pb + (ks * 8 + lt) * SP_STRIDE + nt * 8 + lg]);
        unsigned b1 = __float_as_uint(
            sm[pb + (ks * 8 + lt + 4) * SP_STRIDE + nt * 8 + lg]);
        mma_tf32(s0, qa[0][ks], b0, b1);
        mma_tf32(s1, qa[1][ks], b0, b1);
      }
      float p00 = __expf(s0[0] - SHIFT), p01 = __expf(s0[1] - SHIFT);
      float p02 = __expf(s0[2] - SHIFT), p03 = __expf(s0[3] - SHIFT);
      float p10 = __expf(s1[0] - SHIFT), p11 = __expf(s1[1] - SHIFT);
      float p12 = __expf(s1[2] - SHIFT), p13 = __expf(s1[3] - SHIFT);
      Ls[0][0] += p00 + p01;
      Ls[0][1] += p02 + p03;
      Ls[1][0] += p10 + p11;
      Ls[1][1] += p12 + p13;
      *(uint2*)&sm[APR + (q0w + lg) * PR_STRIDE + nt * 8 + 2 * lt] =
          make_uint2(tf32_bits(p00), tf32_bits(p01));
      *(uint2*)&sm[APR + (q0w + lg + 8) * PR_STRIDE + nt * 8 + 2 * lt] =
          make_uint2(tf32_bits(p02), tf32_bits(p03));
      *(uint2*)&sm[APR + (q0w + 16 + lg) * PR_STRIDE + nt * 8 + 2 * lt] =
          make_uint2(tf32_bits(p10), tf32_bits(p11));
      *(uint2*)&sm[APR + (q0w + 24 + lg) * PR_STRIDE + nt * 8 + 2 * lt] =
          make_uint2(tf32_bits(p12), tf32_bits(p13));
    }
    __syncwarp();

    // ---- PV (buffer gb) ----
#pragma unroll
    for (int ks = 0; ks < 8; ks++) {
      unsigned pa0[4], pa1[4];
      pa0[0] = __float_as_uint(sm[APR + (q0w + lg) * PR_STRIDE + ks * 8 + lt]);
      pa0[1] =
          __float_as_uint(sm[APR + (q0w + lg + 8) * PR_STRIDE + ks * 8 + lt]);
      pa0[2] =
          __float_as_uint(sm[APR + (q0w + lg) * PR_STRIDE + ks * 8 + lt + 4]);
      pa0[3] = __float_as_uint(
          sm[APR + (q0w + lg + 8) * PR_STRIDE + ks * 8 + lt + 4]);
      pa1[0] =
          __float_as_uint(sm[APR + (q0w + 16 + lg) * PR_STRIDE + ks * 8 + lt]);
      pa1[1] =
          __float_as_uint(sm[APR + (q0w + 24 + lg) * PR_STRIDE + ks * 8 + lt]);
      pa1[2] = __float_as_uint(
          sm[APR + (q0w + 16 + lg) * PR_STRIDE + ks * 8 + lt + 4]);
      pa1[3] = __float_as_uint(
          sm[APR + (q0w + 24 + lg) * PR_STRIDE + ks * 8 + lt + 4]);
#pragma unroll
      for (int dt = 0; dt < 4; dt++) {
        unsigned b0 = __float_as_uint(
            sm[gb + (dt * 8 + lg) * SG_STRIDE + ks * 8 + lt]);
        unsigned b1 = __float_as_uint(
            sm[gb + (dt * 8 + lg) * SG_STRIDE + ks * 8 + lt + 4]);
        mma_tf32(c[0][dt], pa0, b0, b1);
        mma_tf32(c[1][dt], pa1, b0, b1);
      }
    }
  }

#pragma unroll
  for (int r = 0; r < 2; r++)
#pragma unroll
    for (int i = 0; i < 2; i++) {
      float v = Ls[r][i];
      v += __shfl_xor_sync(0xffffffffu, v, 1);
      v += __shfl_xor_sync(0xffffffffu, v, 2);
      Ls[r][i] = 1.f / v;
    }

#pragma unroll
  for (int r = 0; r < 2; r++) {
    int qg = n0 + q0w + r * 16 + lg;
#pragma unroll
    for (int dt = 0; dt < 4; dt++) {
      int d0 = dt * 8 + 2 * lt;
      y[ro + (size_t)d0 * NPIX + qg] = c[r][dt][0] * Ls[r][0];
      y[ro + (size_t)(d0 + 1) * NPIX + qg] = c[r][dt][1] * Ls[r][0];
      y[ro + (size_t)d0 * NPIX + qg + 8] = c[r][dt][2] * Ls[r][1];
      y[ro + (size_t)(d0 + 1) * NPIX + qg + 8] = c[r][dt][3] * Ls[r][1];
    }
  }
}

// ---------------- launch ----------------
static float* sym_addr(const void* sym) {
  void* p = nullptr;
  cudaGetSymbolAddress(&p, sym);
  return (float*)p;
}

extern "C" void kernel_launch(void* const* d_in, const int* in_sizes, int n_in,
                              void* d_out, int out_size) {
  const float* x = (const float*)d_in[0];
  const float* g_w = (const float*)d_in[1];
  const float* g_b = (const float*)d_in[2];
  const float* th_w = (const float*)d_in[3];
  const float* th_b = (const float*)d_in[4];
  const float* ph_w = (const float*)d_in[5];
  const float* ph_b = (const float*)d_in[6];
  const float* W_w = (const float*)d_in[7];
  const float* W_b = (const float*)d_in[8];
  const float* bnW_s = (const float*)d_in[9];
  const float* bnW_b = (const float*)d_in[10];
  const float* bnW_m = (const float*)d_in[11];
  const float* bnW_v = (const float*)d_in[12];
  const float* ff1_w = (const float*)d_in[13];
  const float* bn1_s = (const float*)d_in[14];
  const float* bn1_b = (const float*)d_in[15];
  const float* bn1_m = (const float*)d_in[16];
  const float* bn1_v = (const float*)d_in[17];
  const float* ff2_w = (const float*)d_in[18];
  const float* bn2_s = (const float*)d_in[19];
  const float* bn2_b = (const float*)d_in[20];
  const float* bn2_m = (const float*)d_in[21];
  const float* bn2_v = (const float*)d_in[22];
  const float* ff3_w = (const float*)d_in[23];
  const float* bn3_s = (const float*)d_in[24];
  const float* bn3_b = (const float*)d_in[25];
  const float* bn3_m = (const float*)d_in[26];
  const float* bn3_v = (const float*)d_in[27];
  float* out = (float*)d_out;

  float* gb = sym_addr(d_gbuf);
  float* tb = sym_addr(d_tbuf);
  float* pb = sym_addr(d_pbuf);
  float* yb = sym_addr(d_ybuf);
  float* zb = sym_addr(d_zbuf);
  float* o1 = sym_addr(d_o1buf);
  float* o2 = sym_addr(d_o2buf);

  const int PT = BB * 49;  // 196 pixel-tile blocks (64 px each)
  dim3 blk(128);
  const int attn_smem = SMEM_ATT * (int)sizeof(float);  // 55296 B
  static int attr_set = 0;
  if (!attr_set) {
    cudaFuncSetAttribute(attn_k, cudaFuncAttributeMaxDynamicSharedMemorySize,
                         attn_smem);
    attr_set = 1;
  }

  // fused g / theta / phi GEMMs : C -> IC, +bias, tf32-rounded
  gtp_k<<<dim3(PT, 6), blk>>>(x, g_w, g_b, th_w, th_b, ph_w, ph_b, gb, tb, pb);

  // grouped non-local attention (cp.async double-buffered pipeline)
  attn_k<<<dim3(NPIX / 64, GG, BB), dim3(64), attn_smem>>>(tb, pb, gb, yb);

  // W conv: IC -> C, +bias, BN, +x, ReLU -> z
  gemm1x1_k<1><<<dim3(PT, CC / 64), blk>>>(yb, W_w, W_b, bnW_s, bnW_b, bnW_m,
                                           bnW_v, x, zb, ICH, CC);

  // ff1: C -> C4, BN, ReLU -> o1
  gemm1x1_k<2><<<dim3(PT, C4 / 64), blk>>>(zb, ff1_w, nullptr, bn1_s, bn1_b,
                                           bn1_m, bn1_v, nullptr, o1, CC, C4);

  // ff2: 3x3 conv C4 -> C4, BN, ReLU -> o2 (implicit GEMM)
  conv3x3_k<<<dim3(PT), blk>>>(o1, ff2_w, bn2_s, bn2_b, bn2_m, bn2_v, o2);

  // ff3: C4 -> C, BN, +z, ReLU -> out
  gemm1x1_k<3><<<dim3(PT, CC / 64), blk>>>(o2, ff3_w, nullptr, bn3_s, bn3_b,
                                           bn3_m, bn3_v, zb, out, C4, CC);
  (void)in_sizes;
  (void)n_in;
  (void)out_size;
}

// round 14
// speedup vs baseline: 1.1646x; 1.1646x over previous
#include <cuda_runtime.h>
#include <math.h>

#define NPIX 3136
#define HH 56
#define WW 56
#define BB 4
#define CC 256
#define ICH 128
#define GG 4
#define DD 32
#define C4 64
#define EPSB 1e-5f
#define SHIFT 10.0f
#define GS 72  // shared input tile stride (conflict-free for mma B-frag gather)

// ---------------- scratch ----------------
__device__ float d_gbuf[BB * ICH * NPIX];
__device__ float d_tbuf[BB * ICH * NPIX];
__device__ float d_pbuf[BB * ICH * NPIX];
__device__ float d_ybuf[BB * ICH * NPIX];
__device__ float d_zbuf[BB * CC * NPIX];
__device__ float d_o1buf[BB * C4 * NPIX];
__device__ float d_o2buf[BB * C4 * NPIX];

__device__ __forceinline__ float tf32_round(float v) {
  unsigned u;
  asm("cvt.rna.tf32.f32 %0, %1;" : "=r"(u) : "f"(v));
  return __uint_as_float(u);
}
__device__ __forceinline__ unsigned tf32_bits(float v) {
  unsigned u;
  asm("cvt.rna.tf32.f32 %0, %1;" : "=r"(u) : "f"(v));
  return u;
}
__device__ __forceinline__ void mma_tf32(float c[4], const unsigned a[4],
                                         unsigned b0, unsigned b1) {
  asm volatile(
      "mma.sync.aligned.m16n8k8.row.col.f32.tf32.tf32.f32 "
      "{%0,%1,%2,%3}, {%4,%5,%6,%7}, {%8,%9}, {%0,%1,%2,%3};"
      : "+f"(c[0]), "+f"(c[1]), "+f"(c[2]), "+f"(c[3])
      : "r"(a[0]), "r"(a[1]), "r"(a[2]), "r"(a[3]), "r"(b0), "r"(b1));
}

// ---------------- GEMM core: 64 Cout rows x 64 px cols per block (R4) --------
__device__ __forceinline__ void gemm_core(const float* __restrict__ inb,
                                          const float* __restrict__ w, int Cin,
                                          int o0, int tid, float* s_in,
                                          float (&c)[8][4]) {
  const int lane = tid & 31;
  const int lg = lane >> 2, lt = lane & 3;
  const int lr = tid >> 4;         // 0..7
  const int lc = (tid & 15) * 4;   // 0..60

  for (int k0 = 0; k0 < Cin; k0 += 32) {
    __syncthreads();
#pragma unroll
    for (int i = 0; i < 4; i++) {
      int r = i * 8 + lr;
      float4 v = *(const float4*)(inb + (size_t)(k0 + r) * NPIX + lc);
      v.x = tf32_round(v.x);
      v.y = tf32_round(v.y);
      v.z = tf32_round(v.z);
      v.w = tf32_round(v.w);
      *(float4*)&s_in[r * GS + lc] = v;
    }
    __syncthreads();
#pragma unroll
    for (int ks = 0; ks < 4; ks++) {
      int kk = k0 + ks * 8;
      unsigned a[4];
      a[0] = tf32_bits(w[(size_t)(o0 + lg) * Cin + kk + lt]);
      a[1] = tf32_bits(w[(size_t)(o0 + lg + 8) * Cin + kk + lt]);
      a[2] = tf32_bits(w[(size_t)(o0 + lg) * Cin + kk + lt + 4]);
      a[3] = tf32_bits(w[(size_t)(o0 + lg + 8) * Cin + kk + lt + 4]);
#pragma unroll
      for (int nt = 0; nt < 8; nt++) {
        unsigned b0 = __float_as_uint(s_in[(ks * 8 + lt) * GS + nt * 8 + lg]);
        unsigned b1 =
            __float_as_uint(s_in[(ks * 8 + lt + 4) * GS + nt * 8 + lg]);
        mma_tf32(c[nt], a, b0, b1);
      }
    }
  }
}

// ---------------- fused g/theta/phi GEMM (MODE 0: +bias, tf32 round) ---------
__global__ __launch_bounds__(128) void gtp_k(
    const float* __restrict__ x, const float* __restrict__ w0,
    const float* __restrict__ bi0, const float* __restrict__ w1,
    const float* __restrict__ bi1, const float* __restrict__ w2,
    const float* __restrict__ bi2, float* __restrict__ out0,
    float* __restrict__ out1, float* __restrict__ out2) {
  __shared__ float s_in[32 * GS];
  const int tid = threadIdx.x;
  const int lane = tid & 31, wp = tid >> 5;
  const int lg = lane >> 2, lt = lane & 3;
  const int b = blockIdx.x / 49;
  const int px0 = (blockIdx.x % 49) * 64;
  const int sel = blockIdx.y >> 1;
  const int o0 = (blockIdx.y & 1) * 64 + wp * 16;

  const float* w = sel == 0 ? w0 : (sel == 1 ? w1 : w2);
  const float* bi = sel == 0 ? bi0 : (sel == 1 ? bi1 : bi2);
  float* out = sel == 0 ? out0 : (sel == 1 ? out1 : out2);

  float c[8][4] = {};
  gemm_core(x + (size_t)b * CC * NPIX + px0, w, CC, o0, tid, s_in, c);

  int r0 = o0 + lg, r1 = r0 + 8;
  float bb0 = bi[r0], bb1 = bi[r1];
  float* ob0 = out + ((size_t)b * ICH + r0) * NPIX + px0;
  float* ob1 = out + ((size_t)b * ICH + r1) * NPIX + px0;
#pragma unroll
  for (int nt = 0; nt < 8; nt++) {
    int n = nt * 8 + 2 * lt;
    float2 v0 =
        make_float2(tf32_round(c[nt][0] + bb0), tf32_round(c[nt][1] + bb0));
    float2 v1 =
        make_float2(tf32_round(c[nt][2] + bb1), tf32_round(c[nt][3] + bb1));
    *(float2*)(ob0 + n) = v0;
    *(float2*)(ob1 + n) = v1;
  }
}

// ---------------- generic 1x1 GEMM with epilogues (R4) ----------------
// MODE 1: +bias, BN, +res, ReLU   MODE 2: BN, ReLU   MODE 3: BN, +res, ReLU
template <int MODE>
__global__ __launch_bounds__(128) void gemm1x1_k(
    const float* __restrict__ in, const float* __restrict__ w,
    const float* __restrict__ bias, const float* __restrict__ bns,
    const float* __restrict__ bnb, const float* __restrict__ bnm,
    const float* __restrict__ bnv, const float* __restrict__ res,
    float* __restrict__ out, int Cin, int Cout) {
  __shared__ float s_in[32 * GS];
  const int tid = threadIdx.x;
  const int lane = tid & 31, wp = tid >> 5;
  const int lg = lane >> 2, lt = lane & 3;
  const int b = blockIdx.x / 49;
  const int px0 = (blockIdx.x % 49) * 64;
  const int o0 = blockIdx.y * 64 + wp * 16;

  float c[8][4] = {};
  gemm_core(in + (size_t)b * Cin * NPIX + px0, w, Cin, o0, tid, s_in, c);

  int r0 = o0 + lg, r1 = r0 + 8;
  float bi0 = (MODE == 1) ? bias[r0] : 0.f;
  float bi1 = (MODE == 1) ? bias[r1] : 0.f;
  float i0 = bns[r0] * rsqrtf(bnv[r0] + EPSB);
  float a0 = bnb[r0] - bnm[r0] * i0 + bi0 * i0;
  float i1 = bns[r1] * rsqrtf(bnv[r1] + EPSB);
  float a1 = bnb[r1] - bnm[r1] * i1 + bi1 * i1;

  float* ob0 = out + ((size_t)b * Cout + r0) * NPIX + px0;
  float* ob1 = out + ((size_t)b * Cout + r1) * NPIX + px0;
  const float* rb0 = res ? res + ((size_t)b * Cout + r0) * NPIX + px0 : nullptr;
  const float* rb1 = res ? res + ((size_t)b * Cout + r1) * NPIX + px0 : nullptr;
#pragma unroll
  for (int nt = 0; nt < 8; nt++) {
    int n = nt * 8 + 2 * lt;
    float v00 = c[nt][0] * i0 + a0;
    float v01 = c[nt][1] * i0 + a0;
    float v10 = c[nt][2] * i1 + a1;
    float v11 = c[nt][3] * i1 + a1;
    if (MODE == 1 || MODE == 3) {
      float2 q0 = *(const float2*)(rb0 + n);
      float2 q1 = *(const float2*)(rb1 + n);
      v00 += q0.x;
      v01 += q0.y;
      v10 += q1.x;
      v11 += q1.y;
    }
    *(float2*)(ob0 + n) = make_float2(fmaxf(v00, 0.f), fmaxf(v01, 0.f));
    *(float2*)(ob1 + n) = make_float2(fmaxf(v10, 0.f), fmaxf(v11, 0.f));
  }
}

// ---------------- 3x3 conv as implicit GEMM (R4) ----------------
__global__ __launch_bounds__(128) void conv3x3_k(
    const float* __restrict__ in, const float* __restrict__ w,
    const float* __restrict__ bns, const float* __restrict__ bnb,
    const float* __restrict__ bnm, const float* __restrict__ bnv,
    float* __restrict__ out) {
  __shared__ float s_in[32 * GS];
  const int tid = threadIdx.x;
  const int lane = tid & 31, wp = tid >> 5;
  const int lg = lane >> 2, lt = lane & 3;
  const int b = blockIdx.x / 49;
  const int px0 = (blockIdx.x % 49) * 64;
  const int o0 = wp * 16;
  const float* inb = in + (size_t)b * C4 * NPIX;

  const int j = tid & 63;
  const int crow = tid >> 6;
  const int pix = px0 + j;
  const int ph = pix / WW, pw = pix % WW;

  float c[8][4] = {};

#pragma unroll
  for (int kk = 0; kk < 9; kk++) {
    const int dy = kk / 3 - 1, dx = kk % 3 - 1;
    const int hs = ph + dy, ws = pw + dx;
    const bool valid = ((unsigned)hs < HH) && ((unsigned)ws < WW);
    const int src = hs * WW + ws;
#pragma unroll
    for (int k0 = 0; k0 < C4; k0 += 32) {
      __syncthreads();
#pragma unroll
      for (int i = 0; i < 16; i++) {
        int cl = crow + 2 * i;
        float v = valid ? inb[(size_t)(k0 + cl) * NPIX + src] : 0.f;
        s_in[cl * GS + j] = tf32_round(v);
      }
      __syncthreads();
#pragma unroll
      for (int ks = 0; ks < 4; ks++) {
        int ic = k0 + ks * 8;
        unsigned a[4];
        a[0] = tf32_bits(w[(size_t)(o0 + lg) * (C4 * 9) + (ic + lt) * 9 + kk]);
        a[1] =
            tf32_bits(w[(size_t)(o0 + lg + 8) * (C4 * 9) + (ic + lt) * 9 + kk]);
        a[2] =
            tf32_bits(w[(size_t)(o0 + lg) * (C4 * 9) + (ic + lt + 4) * 9 + kk]);
        a[3] = tf32_bits(
            w[(size_t)(o0 + lg + 8) * (C4 * 9) + (ic + lt + 4) * 9 + kk]);
#pragma unroll
        for (int nt = 0; nt < 8; nt++) {
          unsigned b0 = __float_as_uint(s_in[(ks * 8 + lt) * GS + nt * 8 + lg]);
          unsigned b1 =
              __float_as_uint(s_in[(ks * 8 + lt + 4) * GS + nt * 8 + lg]);
          mma_tf32(c[nt], a, b0, b1);
        }
      }
    }
  }

  int r0 = o0 + lg, r1 = r0 + 8;
  float i0 = bns[r0] * rsqrtf(bnv[r0] + EPSB);
  float a0 = bnb[r0] - bnm[r0] * i0;
  float i1 = bns[r1] * rsqrtf(bnv[r1] + EPSB);
  float a1 = bnb[r1] - bnm[r1] * i1;
  float* ob0 = out + ((size_t)b * C4 + r0) * NPIX + px0;
  float* ob1 = out + ((size_t)b * C4 + r1) * NPIX + px0;
#pragma unroll
  for (int nt = 0; nt < 8; nt++) {
    int n = nt * 8 + 2 * lt;
    *(float2*)(ob0 + n) = make_float2(fmaxf(c[nt][0] * i0 + a0, 0.f),
                                      fmaxf(c[nt][1] * i0 + a0, 0.f));
    *(float2*)(ob1 + n) = make_float2(fmaxf(c[nt][2] * i1 + a1, 0.f),
                                      fmaxf(c[nt][3] * i1 + a1, 0.f));
  }
}

// ---- tf32 mma flash attention: R4 body, PV interleaved per key-group --------
// Probs buffer shrinks to parity-double-buffered per-warp [32][12]: smem
// 37.4 KB -> 24.1 KB => ~9 blocks/SM (was ~6). Same math, same LDS counts.
#define SP_STRIDE 72
#define SG_STRIDE 68
#define PRS 12  // per-warp probs stride: lg*12+lt mod 32 all-distinct (CF read)
#define SP_OFF 0
#define SG_OFF (32 * SP_STRIDE)
#define PR_OFF (SG_OFF + 32 * SG_STRIDE)
#define SMEM_AI (PR_OFF + 4 * 32 * PRS)  // 2 parities x 2 warps x 32 x 12

__global__ __launch_bounds__(64) void attn_k(const float* __restrict__ t,
                                             const float* __restrict__ p,
                                             const float* __restrict__ g,
                                             float* __restrict__ y) {
  __shared__ float sm[SMEM_AI];

  const int tid = threadIdx.x;
  const int lane = tid & 31;
  const int wp = tid >> 5;
  const int lg = lane >> 2;
  const int lt = lane & 3;
  const int q0w = wp * 32;
  const int n0 = blockIdx.x * 64;
  const int gi = blockIdx.y;
  const int b = blockIdx.z;
  const size_t ro = ((size_t)b * ICH + gi * DD) * NPIX;

  unsigned qa[2][4][4];
#pragma unroll
  for (int r = 0; r < 2; r++) {
    int qb = n0 + q0w + r * 16;
#pragma unroll
    for (int ks = 0; ks < 4; ks++) {
      int d0 = ks * 8 + lt;
      qa[r][ks][0] = __float_as_uint(t[ro + (size_t)d0 * NPIX + qb + lg]);
      qa[r][ks][1] = __float_as_uint(t[ro + (size_t)d0 * NPIX + qb + lg + 8]);
      qa[r][ks][2] = __float_as_uint(t[ro + (size_t)(d0 + 4) * NPIX + qb + lg]);
      qa[r][ks][3] =
          __float_as_uint(t[ro + (size_t)(d0 + 4) * NPIX + qb + lg + 8]);
    }
  }

  float c[2][4][4];
#pragma unroll
  for (int r = 0; r < 2; r++)
#pragma unroll
    for (int dt = 0; dt < 4; dt++)
#pragma unroll
      for (int i = 0; i < 4; i++) c[r][dt][i] = 0.f;
  float Ls[2][2] = {{0.f, 0.f}, {0.f, 0.f}};

  const int lrow4 = tid >> 4;
  const int lcol = (tid & 15) * 4;

  for (int kt = 0; kt < NPIX / 64; kt++) {
    const int k0 = kt * 64;
    __syncthreads();
#pragma unroll
    for (int i = 0; i < 8; i++) {
      int r = i * 4 + lrow4;
      float4 vp = *(const float4*)(p + ro + (size_t)r * NPIX + k0 + lcol);
      float4 vg = *(const float4*)(g + ro + (size_t)r * NPIX + k0 + lcol);
      *(float4*)&sm[SP_OFF + r * SP_STRIDE + lcol] = vp;
      *(float4*)&sm[SG_OFF + r * SG_STRIDE + lcol] = vg;
    }
    __syncthreads();

#pragma unroll
    for (int nt = 0; nt < 8; nt++) {
      // ---- QK for this 8-key group ----
      float s0[4] = {0.f, 0.f, 0.f, 0.f};
      float s1[4] = {0.f, 0.f, 0.f, 0.f};
#pragma unroll
      for (int ks = 0; ks < 4; ks++) {
        unsigned b0 = __float_as_uint(
            sm[SP_OFF + (ks * 8 + lt) * SP_STRIDE + nt * 8 + lg]);
        unsigned b1 = __float_as_uint(
            sm[SP_OFF + (ks * 8 + lt + 4) * SP_STRIDE + nt * 8 + lg]);
        mma_tf32(s0, qa[0][ks], b0, b1);
        mma_tf32(s1, qa[1][ks], b0, b1);
      }
      float p00 = __expf(s0[0] - SHIFT), p01 = __expf(s0[1] - SHIFT);
      float p02 = __expf(s0[2] - SHIFT), p03 = __expf(s0[3] - SHIFT);
      float p10 = __expf(s1[0] - SHIFT), p11 = __expf(s1[1] - SHIFT);
      float p12 = __expf(s1[2] - SHIFT), p13 = __expf(s1[3] - SHIFT);
      Ls[0][0] += p00 + p01;
      Ls[0][1] += p02 + p03;
      Ls[1][0] += p10 + p11;
      Ls[1][1] += p12 + p13;

      // ---- stage probs to the parity/warp-private [32][12] buffer ----
      const int prw = PR_OFF + ((nt & 1) * 2 + wp) * (32 * PRS);
      *(uint2*)&sm[prw + lg * PRS + 2 * lt] =
          make_uint2(tf32_bits(p00), tf32_bits(p01));
      *(uint2*)&sm[prw + (lg + 8) * PRS + 2 * lt] =
          make_uint2(tf32_bits(p02), tf32_bits(p03));
      *(uint2*)&sm[prw + (lg + 16) * PRS + 2 * lt] =
          make_uint2(tf32_bits(p10), tf32_bits(p11));
      *(uint2*)&sm[prw + (lg + 24) * PRS + 2 * lt] =
          make_uint2(tf32_bits(p12), tf32_bits(p13));
      __syncwarp();

      // ---- gather PV A-fragments (conflict-free: lg*12+lt distinct mod 32) --
      unsigned pa0[4], pa1[4];
      pa0[0] = __float_as_uint(sm[prw + lg * PRS + lt]);
      pa0[1] = __float_as_uint(sm[prw + (lg + 8) * PRS + lt]);
      pa0[2] = __float_as_uint(sm[prw + lg * PRS + lt + 4]);
      pa0[3] = __float_as_uint(sm[prw + (lg + 8) * PRS + lt + 4]);
      pa1[0] = __float_as_uint(sm[prw + (lg + 16) * PRS + lt]);
      pa1[1] = __float_as_uint(sm[prw + (lg + 24) * PRS + lt]);
      pa1[2] = __float_as_uint(sm[prw + (lg + 16) * PRS + lt + 4]);
      pa1[3] = __float_as_uint(sm[prw + (lg + 24) * PRS + lt + 4]);

      // ---- PV for this key group (ks = nt) ----
#pragma unroll
      for (int dt = 0; dt < 4; dt++) {
        unsigned b0 = __float_as_uint(
            sm[SG_OFF + (dt * 8 + lg) * SG_STRIDE + nt * 8 + lt]);
        unsigned b1 = __float_as_uint(
            sm[SG_OFF + (dt * 8 + lg) * SG_STRIDE + nt * 8 + lt + 4]);
        mma_tf32(c[0][dt], pa0, b0, b1);
        mma_tf32(c[1][dt], pa1, b0, b1);
      }
    }
  }

#pragma unroll
  for (int r = 0; r < 2; r++)
#pragma unroll
    for (int i = 0; i < 2; i++) {
      float v = Ls[r][i];
      v += __shfl_xor_sync(0xffffffffu, v, 1);
      v += __shfl_xor_sync(0xffffffffu, v, 2);
      Ls[r][i] = 1.f / v;
    }

#pragma unroll
  for (int r = 0; r < 2; r++) {
    int qg = n0 + q0w + r * 16 + lg;
#pragma unroll
    for (int dt = 0; dt < 4; dt++) {
      int d0 = dt * 8 + 2 * lt;
      y[ro + (size_t)d0 * NPIX + qg] = c[r][dt][0] * Ls[r][0];
      y[ro + (size_t)(d0 + 1) * NPIX + qg] = c[r][dt][1] * Ls[r][0];
      y[ro + (size_t)d0 * NPIX + qg + 8] = c[r][dt][2] * Ls[r][1];
      y[ro + (size_t)(d0 + 1) * NPIX + qg + 8] = c[r][dt][3] * Ls[r][1];
    }
  }
}

// ---------------- launch ----------------
static float* sym_addr(const void* sym) {
  void* p = nullptr;
  cudaGetSymbolAddress(&p, sym);
  return (float*)p;
}

extern "C" void kernel_launch(void* const* d_in, const int* in_sizes, int n_in,
                              void* d_out, int out_size) {
  const float* x = (const float*)d_in[0];
  const float* g_w = (const float*)d_in[1];
  const float* g_b = (const float*)d_in[2];
  const float* th_w = (const float*)d_in[3];
  const float* th_b = (const float*)d_in[4];
  const float* ph_w = (const float*)d_in[5];
  const float* ph_b = (const float*)d_in[6];
  const float* W_w = (const float*)d_in[7];
  const float* W_b = (const float*)d_in[8];
  const float* bnW_s = (const float*)d_in[9];
  const float* bnW_b = (const float*)d_in[10];
  const float* bnW_m = (const float*)d_in[11];
  const float* bnW_v = (const float*)d_in[12];
  const float* ff1_w = (const float*)d_in[13];
  const float* bn1_s = (const float*)d_in[14];
  const float* bn1_b = (const float*)d_in[15];
  const float* bn1_m = (const float*)d_in[16];
  const float* bn1_v = (const float*)d_in[17];
  const float* ff2_w = (const float*)d_in[18];
  const float* bn2_s = (const float*)d_in[19];
  const float* bn2_b = (const float*)d_in[20];
  const float* bn2_m = (const float*)d_in[21];
  const float* bn2_v = (const float*)d_in[22];
  const float* ff3_w = (const float*)d_in[23];
  const float* bn3_s = (const float*)d_in[24];
  const float* bn3_b = (const float*)d_in[25];
  const float* bn3_m = (const float*)d_in[26];
  const float* bn3_v = (const float*)d_in[27];
  float* out = (float*)d_out;

  float* gb = sym_addr(d_gbuf);
  float* tb = sym_addr(d_tbuf);
  float* pb = sym_addr(d_pbuf);
  float* yb = sym_addr(d_ybuf);
  float* zb = sym_addr(d_zbuf);
  float* o1 = sym_addr(d_o1buf);
  float* o2 = sym_addr(d_o2buf);

  const int PT = BB * 49;  // 196 pixel-tile blocks (64 px each)
  dim3 blk(128);

  // fused g / theta / phi GEMMs : C -> IC, +bias, tf32-rounded
  gtp_k<<<dim3(PT, 6), blk>>>(x, g_w, g_b, th_w, th_b, ph_w, ph_b, gb, tb, pb);

  // grouped non-local attention (interleaved QK/PV, 24 KB smem)
  attn_k<<<dim3(NPIX / 64, GG, BB), dim3(64)>>>(tb, pb, gb, yb);

  // W conv: IC -> C, +bias, BN, +x, ReLU -> z
  gemm1x1_k<1><<<dim3(PT, CC / 64), blk>>>(yb, W_w, W_b, bnW_s, bnW_b, bnW_m,
                                           bnW_v, x, zb, ICH, CC);

  // ff1: C -> C4, BN, ReLU -> o1
  gemm1x1_k<2><<<dim3(PT, C4 / 64), blk>>>(zb, ff1_w, nullptr, bn1_s, bn1_b,
                                           bn1_m, bn1_v, nullptr, o1, CC, C4);

  // ff2: 3x3 conv C4 -> C4, BN, ReLU -> o2 (implicit GEMM)
  conv3x3_k<<<dim3(PT), blk>>>(o1, ff2_w, bn2_s, bn2_b, bn2_m, bn2_v, o2);

  // ff3: C4 -> C, BN, +z, ReLU -> out
  gemm1x1_k<3><<<dim3(PT, CC / 64), blk>>>(o2, ff3_w, nullptr, bn3_s, bn3_b,
                                           bn3_m, bn3_v, zb, out, C4, CC);
  (void)in_sizes;
  (void)n_in;
  (void)out_size;
}

// round 15
// speedup vs baseline: 1.2531x; 1.0760x over previous
#include <cuda_runtime.h>
#include <math.h>

#define NPIX 3136
#define HH 56
#define WW 56
#define BB 4
#define CC 256
#define ICH 128
#define GG 4
#define DD 32
#define C4 64
#define EPSB 1e-5f
#define SHIFT 10.0f
#define GS 72  // shared input tile stride (conflict-free for mma B-frag gather)

// ---------------- scratch ----------------
__device__ float d_gbuf[BB * ICH * NPIX];
__device__ float d_tbuf[BB * ICH * NPIX];
__device__ float d_pbuf[BB * ICH * NPIX];
__device__ float d_ybuf[BB * ICH * NPIX];
__device__ float d_zbuf[BB * CC * NPIX];
__device__ float d_o1buf[BB * C4 * NPIX];
__device__ float d_o2buf[BB * C4 * NPIX];

__device__ __forceinline__ float tf32_round(float v) {
  unsigned u;
  asm("cvt.rna.tf32.f32 %0, %1;" : "=r"(u) : "f"(v));
  return __uint_as_float(u);
}
__device__ __forceinline__ unsigned tf32_bits(float v) {
  unsigned u;
  asm("cvt.rna.tf32.f32 %0, %1;" : "=r"(u) : "f"(v));
  return u;
}
__device__ __forceinline__ void mma_tf32(float c[4], const unsigned a[4],
                                         unsigned b0, unsigned b1) {
  asm volatile(
      "mma.sync.aligned.m16n8k8.row.col.f32.tf32.tf32.f32 "
      "{%0,%1,%2,%3}, {%4,%5,%6,%7}, {%8,%9}, {%0,%1,%2,%3};"
      : "+f"(c[0]), "+f"(c[1]), "+f"(c[2]), "+f"(c[3])
      : "r"(a[0]), "r"(a[1]), "r"(a[2]), "r"(a[3]), "r"(b0), "r"(b1));
}

// ---------------- GEMM core: 64 Cout rows x 64 px cols per block (R4) --------
__device__ __forceinline__ void gemm_core(const float* __restrict__ inb,
                                          const float* __restrict__ w, int Cin,
                                          int o0, int tid, float* s_in,
                                          float (&c)[8][4]) {
  const int lane = tid & 31;
  const int lg = lane >> 2, lt = lane & 3;
  const int lr = tid >> 4;         // 0..7
  const int lc = (tid & 15) * 4;   // 0..60

  for (int k0 = 0; k0 < Cin; k0 += 32) {
    __syncthreads();
#pragma unroll
    for (int i = 0; i < 4; i++) {
      int r = i * 8 + lr;
      float4 v = *(const float4*)(inb + (size_t)(k0 + r) * NPIX + lc);
      v.x = tf32_round(v.x);
      v.y = tf32_round(v.y);
      v.z = tf32_round(v.z);
      v.w = tf32_round(v.w);
      *(float4*)&s_in[r * GS + lc] = v;
    }
    __syncthreads();
#pragma unroll
    for (int ks = 0; ks < 4; ks++) {
      int kk = k0 + ks * 8;
      unsigned a[4];
      a[0] = tf32_bits(w[(size_t)(o0 + lg) * Cin + kk + lt]);
      a[1] = tf32_bits(w[(size_t)(o0 + lg + 8) * Cin + kk + lt]);
      a[2] = tf32_bits(w[(size_t)(o0 + lg) * Cin + kk + lt + 4]);
      a[3] = tf32_bits(w[(size_t)(o0 + lg + 8) * Cin + kk + lt + 4]);
#pragma unroll
      for (int nt = 0; nt < 8; nt++) {
        unsigned b0 = __float_as_uint(s_in[(ks * 8 + lt) * GS + nt * 8 + lg]);
        unsigned b1 =
            __float_as_uint(s_in[(ks * 8 + lt + 4) * GS + nt * 8 + lg]);
        mma_tf32(c[nt], a, b0, b1);
      }
    }
  }
}

// ---------------- fused g/theta/phi GEMM (MODE 0: +bias, tf32 round) ---------
__global__ __launch_bounds__(128) void gtp_k(
    const float* __restrict__ x, const float* __restrict__ w0,
    const float* __restrict__ bi0, const float* __restrict__ w1,
    const float* __restrict__ bi1, const float* __restrict__ w2,
    const float* __restrict__ bi2, float* __restrict__ out0,
    float* __restrict__ out1, float* __restrict__ out2) {
  __shared__ float s_in[32 * GS];
  const int tid = threadIdx.x;
  const int lane = tid & 31, wp = tid >> 5;
  const int lg = lane >> 2, lt = lane & 3;
  const int b = blockIdx.x / 49;
  const int px0 = (blockIdx.x % 49) * 64;
  const int sel = blockIdx.y >> 1;
  const int o0 = (blockIdx.y & 1) * 64 + wp * 16;

  const float* w = sel == 0 ? w0 : (sel == 1 ? w1 : w2);
  const float* bi = sel == 0 ? bi0 : (sel == 1 ? bi1 : bi2);
  float* out = sel == 0 ? out0 : (sel == 1 ? out1 : out2);

  float c[8][4] = {};
  gemm_core(x + (size_t)b * CC * NPIX + px0, w, CC, o0, tid, s_in, c);

  int r0 = o0 + lg, r1 = r0 + 8;
  float bb0 = bi[r0], bb1 = bi[r1];
  float* ob0 = out + ((size_t)b * ICH + r0) * NPIX + px0;
  float* ob1 = out + ((size_t)b * ICH + r1) * NPIX + px0;
#pragma unroll
  for (int nt = 0; nt < 8; nt++) {
    int n = nt * 8 + 2 * lt;
    float2 v0 =
        make_float2(tf32_round(c[nt][0] + bb0), tf32_round(c[nt][1] + bb0));
    float2 v1 =
        make_float2(tf32_round(c[nt][2] + bb1), tf32_round(c[nt][3] + bb1));
    *(float2*)(ob0 + n) = v0;
    *(float2*)(ob1 + n) = v1;
  }
}

// ---------------- generic 1x1 GEMM with epilogues (R4) ----------------
// MODE 1: +bias, BN, +res, ReLU   MODE 2: BN, ReLU   MODE 3: BN, +res, ReLU
template <int MODE>
__global__ __launch_bounds__(128) void gemm1x1_k(
    const float* __restrict__ in, const float* __restrict__ w,
    const float* __restrict__ bias, const float* __restrict__ bns,
    const float* __restrict__ bnb, const float* __restrict__ bnm,
    const float* __restrict__ bnv, const float* __restrict__ res,
    float* __restrict__ out, int Cin, int Cout) {
  __shared__ float s_in[32 * GS];
  const int tid = threadIdx.x;
  const int lane = tid & 31, wp = tid >> 5;
  const int lg = lane >> 2, lt = lane & 3;
  const int b = blockIdx.x / 49;
  const int px0 = (blockIdx.x % 49) * 64;
  const int o0 = blockIdx.y * 64 + wp * 16;

  float c[8][4] = {};
  gemm_core(in + (size_t)b * Cin * NPIX + px0, w, Cin, o0, tid, s_in, c);

  int r0 = o0 + lg, r1 = r0 + 8;
  float bi0 = (MODE == 1) ? bias[r0] : 0.f;
  float bi1 = (MODE == 1) ? bias[r1] : 0.f;
  float i0 = bns[r0] * rsqrtf(bnv[r0] + EPSB);
  float a0 = bnb[r0] - bnm[r0] * i0 + bi0 * i0;
  float i1 = bns[r1] * rsqrtf(bnv[r1] + EPSB);
  float a1 = bnb[r1] - bnm[r1] * i1 + bi1 * i1;

  float* ob0 = out + ((size_t)b * Cout + r0) * NPIX + px0;
  float* ob1 = out + ((size_t)b * Cout + r1) * NPIX + px0;
  const float* rb0 = res ? res + ((size_t)b * Cout + r0) * NPIX + px0 : nullptr;
  const float* rb1 = res ? res + ((size_t)b * Cout + r1) * NPIX + px0 : nullptr;
#pragma unroll
  for (int nt = 0; nt < 8; nt++) {
    int n = nt * 8 + 2 * lt;
    float v00 = c[nt][0] * i0 + a0;
    float v01 = c[nt][1] * i0 + a0;
    float v10 = c[nt][2] * i1 + a1;
    float v11 = c[nt][3] * i1 + a1;
    if (MODE == 1 || MODE == 3) {
      float2 q0 = *(const float2*)(rb0 + n);
      float2 q1 = *(const float2*)(rb1 + n);
      v00 += q0.x;
      v01 += q0.y;
      v10 += q1.x;
      v11 += q1.y;
    }
    *(float2*)(ob0 + n) = make_float2(fmaxf(v00, 0.f), fmaxf(v01, 0.f));
    *(float2*)(ob1 + n) = make_float2(fmaxf(v10, 0.f), fmaxf(v11, 0.f));
  }
}

// ---------------- 3x3 conv as implicit GEMM (R4) ----------------
__global__ __launch_bounds__(128) void conv3x3_k(
    const float* __restrict__ in, const float* __restrict__ w,
    const float* __restrict__ bns, const float* __restrict__ bnb,
    const float* __restrict__ bnm, const float* __restrict__ bnv,
    float* __restrict__ out) {
  __shared__ float s_in[32 * GS];
  const int tid = threadIdx.x;
  const int lane = tid & 31, wp = tid >> 5;
  const int lg = lane >> 2, lt = lane & 3;
  const int b = blockIdx.x / 49;
  const int px0 = (blockIdx.x % 49) * 64;
  const int o0 = wp * 16;
  const float* inb = in + (size_t)b * C4 * NPIX;

  const int j = tid & 63;
  const int crow = tid >> 6;
  const int pix = px0 + j;
  const int ph = pix / WW, pw = pix % WW;

  float c[8][4] = {};

#pragma unroll
  for (int kk = 0; kk < 9; kk++) {
    const int dy = kk / 3 - 1, dx = kk % 3 - 1;
    const int hs = ph + dy, ws = pw + dx;
    const bool valid = ((unsigned)hs < HH) && ((unsigned)ws < WW);
    const int src = hs * WW + ws;
#pragma unroll
    for (int k0 = 0; k0 < C4; k0 += 32) {
      __syncthreads();
#pragma unroll
      for (int i = 0; i < 16; i++) {
        int cl = crow + 2 * i;
        float v = valid ? inb[(size_t)(k0 + cl) * NPIX + src] : 0.f;
        s_in[cl * GS + j] = tf32_round(v);
      }
      __syncthreads();
#pragma unroll
      for (int ks = 0; ks < 4; ks++) {
        int ic = k0 + ks * 8;
        unsigned a[4];
        a[0] = tf32_bits(w[(size_t)(o0 + lg) * (C4 * 9) + (ic + lt) * 9 + kk]);
        a[1] =
            tf32_bits(w[(size_t)(o0 + lg + 8) * (C4 * 9) + (ic + lt) * 9 + kk]);
        a[2] =
            tf32_bits(w[(size_t)(o0 + lg) * (C4 * 9) + (ic + lt + 4) * 9 + kk]);
        a[3] = tf32_bits(
            w[(size_t)(o0 + lg + 8) * (C4 * 9) + (ic + lt + 4) * 9 + kk]);
#pragma unroll
        for (int nt = 0; nt < 8; nt++) {
          unsigned b0 = __float_as_uint(s_in[(ks * 8 + lt) * GS + nt * 8 + lg]);
          unsigned b1 =
              __float_as_uint(s_in[(ks * 8 + lt + 4) * GS + nt * 8 + lg]);
          mma_tf32(c[nt], a, b0, b1);
        }
      }
    }
  }

  int r0 = o0 + lg, r1 = r0 + 8;
  float i0 = bns[r0] * rsqrtf(bnv[r0] + EPSB);
  float a0 = bnb[r0] - bnm[r0] * i0;
  float i1 = bns[r1] * rsqrtf(bnv[r1] + EPSB);
  float a1 = bnb[r1] - bnm[r1] * i1;
  float* ob0 = out + ((size_t)b * C4 + r0) * NPIX + px0;
  float* ob1 = out + ((size_t)b * C4 + r1) * NPIX + px0;
#pragma unroll
  for (int nt = 0; nt < 8; nt++) {
    int n = nt * 8 + 2 * lt;
    *(float2*)(ob0 + n) = make_float2(fmaxf(c[nt][0] * i0 + a0, 0.f),
                                      fmaxf(c[nt][1] * i0 + a0, 0.f));
    *(float2*)(ob1 + n) = make_float2(fmaxf(c[nt][2] * i1 + a1, 0.f),
                                      fmaxf(c[nt][3] * i1 + a1, 0.f));
  }
}

// ---- attention: 128 queries/block (4 warps) + interleaved PV, 30 KB smem ----
// Staging (p,g) amortized over 2x queries vs R14: total staging LDG/STS and
// __syncthreads count halve. Per-warp compute body identical to R14.
#define SP_STRIDE 72
#define SG_STRIDE 68
#define PRS 12
#define SP_OFF 0
#define SG_OFF (32 * SP_STRIDE)
#define PR_OFF (SG_OFF + 32 * SG_STRIDE)
#define SMEM_A (PR_OFF + 8 * 32 * PRS)  // 7552 floats = 30.2 KB

__global__ __launch_bounds__(128) void attn_k(const float* __restrict__ t,
                                              const float* __restrict__ p,
                                              const float* __restrict__ g,
                                              float* __restrict__ y) {
  __shared__ float sm[SMEM_A];

  const int tid = threadIdx.x;
  const int lane = tid & 31;
  const int wp = tid >> 5;  // 0..3
  const int lg = lane >> 2;
  const int lt = lane & 3;
  const int q0w = wp * 32;
  const int n0 = blockIdx.x * 128;
  const int gi = blockIdx.y;
  const int b = blockIdx.z;
  const size_t ro = ((size_t)b * ICH + gi * DD) * NPIX;

  // Q fragments (clamped for masked tail tile)
  unsigned qa[2][4][4];
#pragma unroll
  for (int r = 0; r < 2; r++) {
    int qb = n0 + q0w + r * 16;
    int qA = min(qb + lg, NPIX - 1);
    int qB = min(qb + lg + 8, NPIX - 1);
#pragma unroll
    for (int ks = 0; ks < 4; ks++) {
      int d0 = ks * 8 + lt;
      qa[r][ks][0] = __float_as_uint(t[ro + (size_t)d0 * NPIX + qA]);
      qa[r][ks][1] = __float_as_uint(t[ro + (size_t)d0 * NPIX + qB]);
      qa[r][ks][2] = __float_as_uint(t[ro + (size_t)(d0 + 4) * NPIX + qA]);
      qa[r][ks][3] = __float_as_uint(t[ro + (size_t)(d0 + 4) * NPIX + qB]);
    }
  }

  float c[2][4][4];
#pragma unroll
  for (int r = 0; r < 2; r++)
#pragma unroll
    for (int dt = 0; dt < 4; dt++)
#pragma unroll
      for (int i = 0; i < 4; i++) c[r][dt][i] = 0.f;
  float Ls[2][2] = {{0.f, 0.f}, {0.f, 0.f}};

  const int lrow = tid >> 4;        // 0..7
  const int lcol = (tid & 15) * 4;  // 0..60

  for (int kt = 0; kt < NPIX / 64; kt++) {
    const int k0 = kt * 64;
    __syncthreads();
#pragma unroll
    for (int i = 0; i < 4; i++) {
      int r = i * 8 + lrow;
      float4 vp = *(const float4*)(p + ro + (size_t)r * NPIX + k0 + lcol);
      float4 vg = *(const float4*)(g + ro + (size_t)r * NPIX + k0 + lcol);
      *(float4*)&sm[SP_OFF + r * SP_STRIDE + lcol] = vp;
      *(float4*)&sm[SG_OFF + r * SG_STRIDE + lcol] = vg;
    }
    __syncthreads();

#pragma unroll
    for (int nt = 0; nt < 8; nt++) {
      // ---- QK for this 8-key group ----
      float s0[4] = {0.f, 0.f, 0.f, 0.f};
      float s1[4] = {0.f, 0.f, 0.f, 0.f};
#pragma unroll
      for (int ks = 0; ks < 4; ks++) {
        unsigned b0 = __float_as_uint(
            sm[SP_OFF + (ks * 8 + lt) * SP_STRIDE + nt * 8 + lg]);
        unsigned b1 = __float_as_uint(
            sm[SP_OFF + (ks * 8 + lt + 4) * SP_STRIDE + nt * 8 + lg]);
        mma_tf32(s0, qa[0][ks], b0, b1);
        mma_tf32(s1, qa[1][ks], b0, b1);
      }
      float p00 = __expf(s0[0] - SHIFT), p01 = __expf(s0[1] - SHIFT);
      float p02 = __expf(s0[2] - SHIFT), p03 = __expf(s0[3] - SHIFT);
      float p10 = __expf(s1[0] - SHIFT), p11 = __expf(s1[1] - SHIFT);
      float p12 = __expf(s1[2] - SHIFT), p13 = __expf(s1[3] - SHIFT);
      Ls[0][0] += p00 + p01;
      Ls[0][1] += p02 + p03;
      Ls[1][0] += p10 + p11;
      Ls[1][1] += p12 + p13;

      // ---- stage probs to parity/warp-private [32][12] buffer ----
      const int prw = PR_OFF + ((nt & 1) * 4 + wp) * (32 * PRS);
      *(uint2*)&sm[prw + lg * PRS + 2 * lt] =
          make_uint2(tf32_bits(p00), tf32_bits(p01));
      *(uint2*)&sm[prw + (lg + 8) * PRS + 2 * lt] =
          make_uint2(tf32_bits(p02), tf32_bits(p03));
      *(uint2*)&sm[prw + (lg + 16) * PRS + 2 * lt] =
          make_uint2(tf32_bits(p10), tf32_bits(p11));
      *(uint2*)&sm[prw + (lg + 24) * PRS + 2 * lt] =
          make_uint2(tf32_bits(p12), tf32_bits(p13));
      __syncwarp();

      // ---- gather PV A-fragments (lg*12+lt distinct mod 32: CF) ----
      unsigned pa0[4], pa1[4];
      pa0[0] = __float_as_uint(sm[prw + lg * PRS + lt]);
      pa0[1] = __float_as_uint(sm[prw + (lg + 8) * PRS + lt]);
      pa0[2] = __float_as_uint(sm[prw + lg * PRS + lt + 4]);
      pa0[3] = __float_as_uint(sm[prw + (lg + 8) * PRS + lt + 4]);
      pa1[0] = __float_as_uint(sm[prw + (lg + 16) * PRS + lt]);
      pa1[1] = __float_as_uint(sm[prw + (lg + 24) * PRS + lt]);
      pa1[2] = __float_as_uint(sm[prw + (lg + 16) * PRS + lt + 4]);
      pa1[3] = __float_as_uint(sm[prw + (lg + 24) * PRS + lt + 4]);

      // ---- PV for this key group (ks = nt) ----
#pragma unroll
      for (int dt = 0; dt < 4; dt++) {
        unsigned b0 = __float_as_uint(
            sm[SG_OFF + (dt * 8 + lg) * SG_STRIDE + nt * 8 + lt]);
        unsigned b1 = __float_as_uint(
            sm[SG_OFF + (dt * 8 + lg) * SG_STRIDE + nt * 8 + lt + 4]);
        mma_tf32(c[0][dt], pa0, b0, b1);
        mma_tf32(c[1][dt], pa1, b0, b1);
      }
    }
  }

#pragma unroll
  for (int r = 0; r < 2; r++)
#pragma unroll
    for (int i = 0; i < 2; i++) {
      float v = Ls[r][i];
      v += __shfl_xor_sync(0xffffffffu, v, 1);
      v += __shfl_xor_sync(0xffffffffu, v, 2);
      Ls[r][i] = 1.f / v;
    }

#pragma unroll
  for (int r = 0; r < 2; r++) {
    int qg = n0 + q0w + r * 16 + lg;
    bool okA = qg < NPIX;
    bool okB = (qg + 8) < NPIX;
#pragma unroll
    for (int dt = 0; dt < 4; dt++) {
      int d0 = dt * 8 + 2 * lt;
      if (okA) {
        y[ro + (size_t)d0 * NPIX + qg] = c[r][dt][0] * Ls[r][0];
        y[ro + (size_t)(d0 + 1) * NPIX + qg] = c[r][dt][1] * Ls[r][0];
      }
      if (okB) {
        y[ro + (size_t)d0 * NPIX + qg + 8] = c[r][dt][2] * Ls[r][1];
        y[ro + (size_t)(d0 + 1) * NPIX + qg + 8] = c[r][dt][3] * Ls[r][1];
      }
    }
  }
}

// ---------------- launch ----------------
static float* sym_addr(const void* sym) {
  void* p = nullptr;
  cudaGetSymbolAddress(&p, sym);
  return (float*)p;
}

extern "C" void kernel_launch(void* const* d_in, const int* in_sizes, int n_in,
                              void* d_out, int out_size) {
  const float* x = (const float*)d_in[0];
  const float* g_w = (const float*)d_in[1];
  const float* g_b = (const float*)d_in[2];
  const float* th_w = (const float*)d_in[3];
  const float* th_b = (const float*)d_in[4];
  const float* ph_w = (const float*)d_in[5];
  const float* ph_b = (const float*)d_in[6];
  const float* W_w = (const float*)d_in[7];
  const float* W_b = (const float*)d_in[8];
  const float* bnW_s = (const float*)d_in[9];
  const float* bnW_b = (const float*)d_in[10];
  const float* bnW_m = (const float*)d_in[11];
  const float* bnW_v = (const float*)d_in[12];
  const float* ff1_w = (const float*)d_in[13];
  const float* bn1_s = (const float*)d_in[14];
  const float* bn1_b = (const float*)d_in[15];
  const float* bn1_m = (const float*)d_in[16];
  const float* bn1_v = (const float*)d_in[17];
  const float* ff2_w = (const float*)d_in[18];
  const float* bn2_s = (const float*)d_in[19];
  const float* bn2_b = (const float*)d_in[20];
  const float* bn2_m = (const float*)d_in[21];
  const float* bn2_v = (const float*)d_in[22];
  const float* ff3_w = (const float*)d_in[23];
  const float* bn3_s = (const float*)d_in[24];
  const float* bn3_b = (const float*)d_in[25];
  const float* bn3_m = (const float*)d_in[26];
  const float* bn3_v = (const float*)d_in[27];
  float* out = (float*)d_out;

  float* gb = sym_addr(d_gbuf);
  float* tb = sym_addr(d_tbuf);
  float* pb = sym_addr(d_pbuf);
  float* yb = sym_addr(d_ybuf);
  float* zb = sym_addr(d_zbuf);
  float* o1 = sym_addr(d_o1buf);
  float* o2 = sym_addr(d_o2buf);

  const int PT = BB * 49;  // 196 pixel-tile blocks (64 px each)
  dim3 blk(128);

  // fused g / theta / phi GEMMs : C -> IC, +bias, tf32-rounded
  gtp_k<<<dim3(PT, 6), blk>>>(x, g_w, g_b, th_w, th_b, ph_w, ph_b, gb, tb, pb);

  // grouped non-local attention: 128 q/block, interleaved PV, 30 KB smem
  attn_k<<<dim3((NPIX + 127) / 128, GG, BB), dim3(128)>>>(tb, pb, gb, yb);

  // W conv: IC -> C, +bias, BN, +x, ReLU -> z
  gemm1x1_k<1><<<dim3(PT, CC / 64), blk>>>(yb, W_w, W_b, bnW_s, bnW_b, bnW_m,
                                           bnW_v, x, zb, ICH, CC);

  // ff1: C -> C4, BN, ReLU -> o1
  gemm1x1_k<2><<<dim3(PT, C4 / 64), blk>>>(zb, ff1_w, nullptr, bn1_s, bn1_b,
                                           bn1_m, bn1_v, nullptr, o1, CC, C4);

  // ff2: 3x3 conv C4 -> C4, BN, ReLU -> o2 (implicit GEMM)
  conv3x3_k<<<dim3(PT), blk>>>(o1, ff2_w, bn2_s, bn2_b, bn2_m, bn2_v, o2);

  // ff3: C4 -> C, BN, +z, ReLU -> out
  gemm1x1_k<3><<<dim3(PT, CC / 64), blk>>>(o2, ff3_w, nullptr, bn3_s, bn3_b,
                                           bn3_m, bn3_v, zb, out, C4, CC);
  (void)in_sizes;
  (void)n_in;
  (void)out_size;
}